// round 2
// baseline (speedup 1.0000x reference)
#include <cuda_runtime.h>
#include <cuda_bf16.h>
#include <stdint.h>

// ---------------------------------------------------------------------------
// AnnularPatchEmbed:
//   tokens[b,c,d] = sum_p x[b,p] * masks[c,p] * W[d,p]     (rings disjoint!)
//   out[b,c,o]    = sum_d tokens[b,c,d] * fc_w[o,d] + fc_b[o]
//
// Rings are disjoint -> segmented GEMM over a ring-sorted pixel index list
// (built deterministically per launch), fp32 SIMT math.
// ---------------------------------------------------------------------------

#define IMG      224
#define P        (IMG * IMG)       // 50176
#define B        64
#define NRINGS   16
#define TOKD     256
#define OUTD     192
#define NTILES   (P / 256)         // 196
#define KC       192               // K-chunk per GEMM block (load balance)
#define KB       32                // K step inside GEMM block
#define MAXCHUNK 288               // >= P/KC + NRINGS worst case

// ---------------- device scratch (no allocations allowed) -----------------
__device__ unsigned char g_rid[P];
__device__ int   g_tileCnt[NTILES * NRINGS];
__device__ int   g_tileOff[NTILES * NRINGS];
__device__ int   g_ringBase[NRINGS + 1];
__device__ int   g_idx[P];
__device__ int   g_chunkRing[MAXCHUNK];
__device__ int   g_chunkK0[MAXCHUNK];
__device__ int   g_chunkLen[MAXCHUNK];
__device__ int   g_nChunks;
__device__ float4 g_tokens4[(B * NRINGS * TOKD) / 4];   // 1 MB, 16B aligned
__device__ float  g_fcwT[TOKD * OUTD];                  // fc_w transposed [d][o]

// ---------------------------------------------------------------------------
// 0) zero the tokens accumulator
// ---------------------------------------------------------------------------
__global__ void k_zero_tokens() {
    int i = blockIdx.x * blockDim.x + threadIdx.x;    // 65536 float4
    g_tokens4[i] = make_float4(0.f, 0.f, 0.f, 0.f);
}

// ---------------------------------------------------------------------------
// 0b) transpose fc_w [192,256] -> g_fcwT [256,192] (coalesced stage-2 reads)
// ---------------------------------------------------------------------------
__global__ void k_transpose_fcw(const float* __restrict__ fc_w) {
    int idx = blockIdx.x * blockDim.x + threadIdx.x;  // 49152
    if (idx < OUTD * TOKD) {
        int o = idx / TOKD, d = idx % TOKD;
        g_fcwT[d * OUTD + o] = fc_w[idx];
    }
}

// ---------------------------------------------------------------------------
// 1) ring id per pixel (from masks -> exact boundary semantics) + tile counts
// ---------------------------------------------------------------------------
__global__ void k_rid_count(const float* __restrict__ masks) {
    __shared__ int hist[NRINGS];
    int t = threadIdx.x;
    if (t < NRINGS) hist[t] = 0;
    __syncthreads();

    int p = blockIdx.x * 256 + t;
    int r = 255;
#pragma unroll
    for (int c = 0; c < NRINGS; c++)
        if (masks[c * P + p] > 0.5f) r = c;
    g_rid[p] = (unsigned char)r;
    if (r < NRINGS) atomicAdd(&hist[r], 1);
    __syncthreads();
    if (t < NRINGS) g_tileCnt[blockIdx.x * NRINGS + t] = hist[t];
}

// ---------------------------------------------------------------------------
// 2) exclusive scans + chunk descriptor build (single tiny block)
// ---------------------------------------------------------------------------
__global__ void k_scan_chunks() {
    __shared__ int ringTot[NRINGS];
    int t = threadIdx.x;
    if (t < NRINGS) {
        int s = 0;
        for (int i = 0; i < NTILES; i++) {
            g_tileOff[i * NRINGS + t] = s;
            s += g_tileCnt[i * NRINGS + t];
        }
        ringTot[t] = s;
    }
    __syncthreads();
    if (t == 0) {
        int base = 0;
        for (int c = 0; c < NRINGS; c++) { g_ringBase[c] = base; base += ringTot[c]; }
        g_ringBase[NRINGS] = base;
        int nc = 0;
        for (int c = 0; c < NRINGS; c++) {
            for (int k0 = 0; k0 < ringTot[c] && nc < MAXCHUNK; k0 += KC) {
                g_chunkRing[nc] = c;
                g_chunkK0[nc]   = g_ringBase[c] + k0;
                g_chunkLen[nc]  = min(KC, ringTot[c] - k0);
                nc++;
            }
        }
        g_nChunks = nc;
    }
}

// ---------------------------------------------------------------------------
// 3) stable ring-sorted compaction (ballot ranks -> deterministic order)
// ---------------------------------------------------------------------------
__global__ void k_scatter() {
    int t = threadIdx.x;
    int tile = blockIdx.x;
    int p = tile * 256 + t;
    int r = g_rid[p];
    int lane = t & 31, w = t >> 5;
    __shared__ int wcnt[8], wpre[8];

    for (int c = 0; c < NRINGS; c++) {
        bool f = (r == c);
        unsigned bal = __ballot_sync(0xffffffffu, f);
        int lr = __popc(bal & ((1u << lane) - 1u));
        if (lane == 0) wcnt[w] = __popc(bal);
        __syncthreads();
        if (t == 0) {
            int s = 0;
            for (int i = 0; i < 8; i++) { wpre[i] = s; s += wcnt[i]; }
        }
        __syncthreads();
        if (f) {
            int pos = g_ringBase[c] + g_tileOff[tile * NRINGS + c] + wpre[w] + lr;
            g_idx[pos] = p;
        }
        __syncthreads();
    }
}

// ---------------------------------------------------------------------------
// 4) segmented GEMM: tokens[b, ring, d] += x[b,p] * W[d,p] over ring pixels.
//    Block = (K-chunk, d-half). Tile M=64 (all batches) x N=128, fp32.
// ---------------------------------------------------------------------------
__global__ void __launch_bounds__(256, 2)
k_gemm_tokens(const float* __restrict__ x, const float* __restrict__ W) {
    int chunk = blockIdx.x;
    if (chunk >= g_nChunks) return;
    int ring  = g_chunkRing[chunk];
    int kbeg  = g_chunkK0[chunk];
    int klen  = g_chunkLen[chunk];
    int dBase = blockIdx.y * 128;

    __shared__ float As[KB][65];    // As[k][m] = x[m, p_k]
    __shared__ float Bs[KB][129];   // Bs[k][n] = W[dBase+n, p_k]
    __shared__ int   Ps[KB];

    int t   = threadIdx.x;
    int mi  = t >> 4;               // 0..15 -> batches mi*4..mi*4+3
    int ni  = t & 15;               // 0..15 -> cols    ni*8..ni*8+7

    float acc[4][8];
#pragma unroll
    for (int i = 0; i < 4; i++)
#pragma unroll
        for (int j = 0; j < 8; j++) acc[i][j] = 0.f;

    int kLd = t & 31;               // k-slot this thread loads
    int ldB = t >> 5;               // 0..7

    for (int kk = 0; kk < klen; kk += KB) {
        if (t < KB) {
            int k = kk + t;
            Ps[t] = (k < klen) ? g_idx[kbeg + k] : -1;
        }
        __syncthreads();

        int pp = Ps[kLd];
        if (pp >= 0) {
#pragma unroll
            for (int i = 0; i < 2; i++) {
                int m = ldB + 8 * i;                // covers all 64 rows via +16/+32/+48
                As[kLd][m]      = x[m * P + pp];
                As[kLd][m + 16] = x[(m + 16) * P + pp];
                As[kLd][m + 32] = x[(m + 32) * P + pp];
                As[kLd][m + 48] = x[(m + 48) * P + pp];
            }
#pragma unroll
            for (int i = 0; i < 16; i++) {
                int n = ldB + 8 * i;
                Bs[kLd][n] = W[(dBase + n) * P + pp];
            }
        } else {
#pragma unroll
            for (int i = 0; i < 2; i++) {
                int m = ldB + 8 * i;
                As[kLd][m] = 0.f; As[kLd][m + 16] = 0.f;
                As[kLd][m + 32] = 0.f; As[kLd][m + 48] = 0.f;
            }
#pragma unroll
            for (int i = 0; i < 16; i++) Bs[kLd][ldB + 8 * i] = 0.f;
        }
        __syncthreads();

#pragma unroll
        for (int k = 0; k < KB; k++) {
            float a0 = As[k][mi * 4 + 0];
            float a1 = As[k][mi * 4 + 1];
            float a2 = As[k][mi * 4 + 2];
            float a3 = As[k][mi * 4 + 3];
            float b[8];
#pragma unroll
            for (int j = 0; j < 8; j++) b[j] = Bs[k][ni * 8 + j];
#pragma unroll
            for (int j = 0; j < 8; j++) {
                acc[0][j] += a0 * b[j];
                acc[1][j] += a1 * b[j];
                acc[2][j] += a2 * b[j];
                acc[3][j] += a3 * b[j];
            }
        }
        __syncthreads();
    }

    float* tokens = (float*)g_tokens4;
#pragma unroll
    for (int i = 0; i < 4; i++) {
        int b = mi * 4 + i;
        float* dst = tokens + b * (NRINGS * TOKD) + ring * TOKD + dBase + ni * 8;
#pragma unroll
        for (int j = 0; j < 8; j++) atomicAdd(dst + j, acc[i][j]);
    }
}

// ---------------------------------------------------------------------------
// 5) stage 2: out[b,c,o] = bias[o] + sum_d tokens[b,c,d] * fcwT[d,o]
//    grid (64 batches, 2 ring-halves), 192 threads (one per o)
// ---------------------------------------------------------------------------
__global__ void k_stage2(const float* __restrict__ fc_b, float* __restrict__ out) {
    int b   = blockIdx.x;
    int ch0 = blockIdx.y * 8;
    int o   = threadIdx.x;     // 0..191
    __shared__ float4 tok[8][64];

    const float4* src = g_tokens4 + (b * NRINGS + ch0) * (TOKD / 4);
    for (int i = o; i < 8 * 64; i += OUTD)
        tok[i >> 6][i & 63] = src[i];
    __syncthreads();

    float bias = fc_b[o];
    float acc[8];
#pragma unroll
    for (int c = 0; c < 8; c++) acc[c] = bias;

    for (int d4 = 0; d4 < 64; d4++) {
        float w0 = g_fcwT[(d4 * 4 + 0) * OUTD + o];
        float w1 = g_fcwT[(d4 * 4 + 1) * OUTD + o];
        float w2 = g_fcwT[(d4 * 4 + 2) * OUTD + o];
        float w3 = g_fcwT[(d4 * 4 + 3) * OUTD + o];
#pragma unroll
        for (int c = 0; c < 8; c++) {
            float4 tv = tok[c][d4];
            acc[c] += tv.x * w0 + tv.y * w1 + tv.z * w2 + tv.w * w3;
        }
    }
#pragma unroll
    for (int c = 0; c < 8; c++)
        out[b * (NRINGS * OUTD) + (ch0 + c) * OUTD + o] = acc[c];
}

// ---------------------------------------------------------------------------
extern "C" void kernel_launch(void* const* d_in, const int* in_sizes, int n_in,
                              void* d_out, int out_size) {
    // Identify inputs by element count, fall back to metadata position order:
    //   0: x [64,224,224]  1: tokens_weights [256,1,224,224]
    //   2: fc_w [192,256]  3: fc_b [192]  4: masks [16,224,224]
    const float *x = nullptr, *W = nullptr, *fc_w = nullptr, *fc_b = nullptr,
                *masks = nullptr;
    for (int i = 0; i < n_in; i++) {
        switch (in_sizes[i]) {
            case B * P:            x     = (const float*)d_in[i]; break;   // 3211264
            case TOKD * P:         W     = (const float*)d_in[i]; break;   // 12845056
            case OUTD * TOKD:      fc_w  = (const float*)d_in[i]; break;   // 49152
            case OUTD:             fc_b  = (const float*)d_in[i]; break;   // 192
            case NRINGS * P:       masks = (const float*)d_in[i]; break;   // 802816
            default: break;
        }
    }
    if (!x || !W || !fc_w || !fc_b || !masks) {
        x     = (const float*)d_in[0];
        W     = (const float*)d_in[1];
        fc_w  = (const float*)d_in[2];
        fc_b  = (const float*)d_in[3];
        masks = (const float*)d_in[4];
    }
    float* out = (float*)d_out;

    k_zero_tokens   <<<256, 256>>>();
    k_transpose_fcw <<<(OUTD * TOKD + 255) / 256, 256>>>(fc_w);
    k_rid_count     <<<NTILES, 256>>>(masks);
    k_scan_chunks   <<<1, 32>>>();
    k_scatter       <<<NTILES, 256>>>();
    k_gemm_tokens   <<<dim3(MAXCHUNK, 2), 256>>>(x, W);
    k_stage2        <<<dim3(B, 2), OUTD>>>(fc_b, out);
}

// round 4
// speedup vs baseline: 1.3651x; 1.3651x over previous
#include <cuda_runtime.h>
#include <cuda_bf16.h>
#include <stdint.h>

// ---------------------------------------------------------------------------
// AnnularPatchEmbed:
//   tokens[b,c,d] = sum_p x[b,p] * masks[c,p] * W[d,p]     (rings disjoint!)
//   out[b,c,o]    = sum_d tokens[b,c,d] * fc_w[o,d] + fc_b[o]
//
// Rings disjoint -> segmented GEMM over ring-sorted pixel index list.
// R3/R4: parallel tile-offset scan (was 66us serial), match_any scatter,
//        leaner GEMM mainloop (no Ps staging, 2 syncs/iter, 3 blocks/SM).
// ---------------------------------------------------------------------------

#define IMG      224
#define P        (IMG * IMG)       // 50176
#define B        64
#define NRINGS   16
#define TOKD     256
#define OUTD     192
#define NTILES   (P / 256)         // 196
#define KC       192               // K-chunk per GEMM block
#define KB       32                // K step inside GEMM block
#define MAXCHUNK 288               // >= total chunks worst case

// ---------------- device scratch (no allocations allowed) -----------------
__device__ unsigned char g_rid[P];
__device__ int   g_tileCnt[NTILES * NRINGS];
__device__ int   g_tileOff[NTILES * NRINGS];
__device__ int   g_ringBase[NRINGS + 1];
__device__ int   g_idx[P];
__device__ int   g_chunkRing[MAXCHUNK];
__device__ int   g_chunkK0[MAXCHUNK];
__device__ int   g_chunkLen[MAXCHUNK];
__device__ int   g_nChunks;
__device__ float4 g_tokens4[(B * NRINGS * TOKD) / 4];   // 1 MB
__device__ float  g_fcwT[TOKD * OUTD];                  // fc_w transposed

// ---------------------------------------------------------------------------
// 0) zero tokens accumulator
// ---------------------------------------------------------------------------
__global__ void k_zero_tokens() {
    int i = blockIdx.x * blockDim.x + threadIdx.x;    // 65536 float4
    g_tokens4[i] = make_float4(0.f, 0.f, 0.f, 0.f);
}

// ---------------------------------------------------------------------------
// 0b) transpose fc_w [192,256] -> g_fcwT [256,192] (float4 reads)
// ---------------------------------------------------------------------------
__global__ void k_transpose_fcw(const float* __restrict__ fc_w) {
    int idx = blockIdx.x * blockDim.x + threadIdx.x;  // 12288 float4
    if (idx < OUTD * TOKD / 4) {
        int o = idx / (TOKD / 4), d4 = idx % (TOKD / 4);
        float4 v = ((const float4*)fc_w)[idx];
        g_fcwT[(d4 * 4 + 0) * OUTD + o] = v.x;
        g_fcwT[(d4 * 4 + 1) * OUTD + o] = v.y;
        g_fcwT[(d4 * 4 + 2) * OUTD + o] = v.z;
        g_fcwT[(d4 * 4 + 3) * OUTD + o] = v.w;
    }
}

// ---------------------------------------------------------------------------
// 1) ring id per pixel + per-tile ring histograms
// ---------------------------------------------------------------------------
__global__ void k_rid_count(const float* __restrict__ masks) {
    __shared__ int hist[NRINGS];
    int t = threadIdx.x;
    if (t < NRINGS) hist[t] = 0;
    __syncthreads();

    int p = blockIdx.x * 256 + t;
    int r = 255;
#pragma unroll
    for (int c = 0; c < NRINGS; c++)
        if (masks[c * P + p] > 0.5f) r = c;
    g_rid[p] = (unsigned char)r;
    if (r < NRINGS) atomicAdd(&hist[r], 1);
    __syncthreads();
    if (t < NRINGS) g_tileCnt[blockIdx.x * NRINGS + t] = hist[t];
}

// ---------------------------------------------------------------------------
// 2) PARALLEL scans + chunk build. 1 block, 512 threads = 16 warps,
//    warp w scans ring w's 196 tile counts with warp-shuffle scans.
// ---------------------------------------------------------------------------
__global__ void k_scan_chunks() {
    __shared__ int ringTot[NRINGS];
    __shared__ int ringBaseS[NRINGS];
    __shared__ int chunkBaseS[NRINGS];
    int t = threadIdx.x, w = t >> 5, lane = t & 31;

    // per-ring exclusive scan over tiles (7 warp-scan rounds of 32)
    if (w < NRINGS) {
        int run = 0;
        for (int base = 0; base < NTILES; base += 32) {
            int i = base + lane;
            int v = (i < NTILES) ? g_tileCnt[i * NRINGS + w] : 0;
            int s = v;
#pragma unroll
            for (int d = 1; d < 32; d <<= 1) {
                int n = __shfl_up_sync(0xffffffffu, s, d);
                if (lane >= d) s += n;
            }
            if (i < NTILES) g_tileOff[i * NRINGS + w] = run + s - v;
            run += __shfl_sync(0xffffffffu, s, 31);
        }
        if (lane == 0) ringTot[w] = run;
    }
    __syncthreads();

    // warp 0: ring bases + chunk bases (exclusive scans over 16 values)
    if (w == 0) {
        int v = (lane < NRINGS) ? ringTot[lane] : 0;
        int s = v;
#pragma unroll
        for (int d = 1; d < 32; d <<= 1) {
            int n = __shfl_up_sync(0xffffffffu, s, d);
            if (lane >= d) s += n;
        }
        if (lane < NRINGS) { ringBaseS[lane] = s - v; g_ringBase[lane] = s - v; }
        if (lane == NRINGS - 1) g_ringBase[NRINGS] = s;

        int nc = (v + KC - 1) / KC;
        int cs = nc;
#pragma unroll
        for (int d = 1; d < 32; d <<= 1) {
            int n = __shfl_up_sync(0xffffffffu, cs, d);
            if (lane >= d) cs += n;
        }
        if (lane < NRINGS) chunkBaseS[lane] = cs - nc;
        if (lane == NRINGS - 1) g_nChunks = cs;
    }
    __syncthreads();

    // each warp fills its ring's chunk descriptors (<=32 chunks/ring)
    if (w < NRINGS) {
        int tot = ringTot[w];
        int nc  = (tot + KC - 1) / KC;
        if (lane < nc) {
            int g = chunkBaseS[w] + lane;
            int k0 = lane * KC;
            g_chunkRing[g] = w;
            g_chunkK0[g]   = ringBaseS[w] + k0;
            g_chunkLen[g]  = min(KC, tot - k0);
        }
    }
}

// ---------------------------------------------------------------------------
// 3) single-pass stable ring-sorted compaction (match_any ranks)
// ---------------------------------------------------------------------------
__global__ void k_scatter() {
    __shared__ int wcnt[8][NRINGS];
    __shared__ int wpre[8][NRINGS];
    int t = threadIdx.x, tile = blockIdx.x;
    int lane = t & 31, w = t >> 5;

    if (t < 8 * NRINGS) ((int*)wcnt)[t] = 0;
    __syncthreads();

    int p = tile * 256 + t;
    int r = g_rid[p];
    unsigned peers = __match_any_sync(0xffffffffu, r);
    int lr = __popc(peers & ((1u << lane) - 1u));
    bool valid = (r < NRINGS);
    if (valid && lane == (__ffs(peers) - 1)) wcnt[w][r] = __popc(peers);
    __syncthreads();

    if (t < NRINGS) {
        int s = 0;
#pragma unroll
        for (int i = 0; i < 8; i++) { int v = wcnt[i][t]; wpre[i][t] = s; s += v; }
    }
    __syncthreads();

    if (valid) {
        int pos = g_ringBase[r] + g_tileOff[tile * NRINGS + r] + wpre[w][r] + lr;
        g_idx[pos] = p;
    }
}

// ---------------------------------------------------------------------------
// 4) segmented GEMM: tokens[b,ring,d] += x[b,p]*W[d,p] over ring pixels.
//    Block = (K-chunk, d-half). Tile M=64 x N=128 fp32, 3 blocks/SM.
// ---------------------------------------------------------------------------
__global__ void __launch_bounds__(256, 3)
k_gemm_tokens(const float* __restrict__ x, const float* __restrict__ W) {
    int chunk = blockIdx.x;
    if (chunk >= g_nChunks) return;
    int ring  = g_chunkRing[chunk];
    int kbeg  = g_chunkK0[chunk];
    int klen  = g_chunkLen[chunk];
    int dBase = blockIdx.y * 128;

    __shared__ float As[KB][65];    // As[k][m] = x[m, p_k]
    __shared__ float Bs[KB][129];   // Bs[k][n] = W[dBase+n, p_k]

    int t   = threadIdx.x;
    int mi  = t >> 4;               // 0..15
    int ni  = t & 15;               // 0..15

    float acc[4][8];
#pragma unroll
    for (int i = 0; i < 4; i++)
#pragma unroll
        for (int j = 0; j < 8; j++) acc[i][j] = 0.f;

    int kLd = t & 31;               // k-slot this thread loads
    int ldB = t >> 5;               // 0..7

    for (int kk = 0; kk < klen; kk += KB) {
        int k  = kk + kLd;
        int pp = (k < klen) ? g_idx[kbeg + k] : -1;   // coalesced, L1-shared

        if (pp >= 0) {
            {
                int m = ldB;
                As[kLd][m]      = x[m * P + pp];
                As[kLd][m + 16] = x[(m + 16) * P + pp];
                As[kLd][m + 32] = x[(m + 32) * P + pp];
                As[kLd][m + 48] = x[(m + 48) * P + pp];
                m = ldB + 8;
                As[kLd][m]      = x[m * P + pp];
                As[kLd][m + 16] = x[(m + 16) * P + pp];
                As[kLd][m + 32] = x[(m + 32) * P + pp];
                As[kLd][m + 48] = x[(m + 48) * P + pp];
            }
#pragma unroll
            for (int i = 0; i < 16; i++) {
                int n = ldB + 8 * i;
                Bs[kLd][n] = W[(dBase + n) * P + pp];
            }
        } else {
#pragma unroll
            for (int i = 0; i < 2; i++) {
                int m = ldB + 8 * i;
                As[kLd][m] = 0.f; As[kLd][m + 16] = 0.f;
                As[kLd][m + 32] = 0.f; As[kLd][m + 48] = 0.f;
            }
#pragma unroll
            for (int i = 0; i < 16; i++) Bs[kLd][ldB + 8 * i] = 0.f;
        }
        __syncthreads();

#pragma unroll
        for (int k2 = 0; k2 < KB; k2++) {
            float a0 = As[k2][mi * 4 + 0];
            float a1 = As[k2][mi * 4 + 1];
            float a2 = As[k2][mi * 4 + 2];
            float a3 = As[k2][mi * 4 + 3];
            float b[8];
#pragma unroll
            for (int j = 0; j < 8; j++) b[j] = Bs[k2][ni * 8 + j];
#pragma unroll
            for (int j = 0; j < 8; j++) {
                acc[0][j] += a0 * b[j];
                acc[1][j] += a1 * b[j];
                acc[2][j] += a2 * b[j];
                acc[3][j] += a3 * b[j];
            }
        }
        __syncthreads();
    }

    float* tokens = (float*)g_tokens4;
#pragma unroll
    for (int i = 0; i < 4; i++) {
        int b = mi * 4 + i;
        float* dst = tokens + b * (NRINGS * TOKD) + ring * TOKD + dBase + ni * 8;
#pragma unroll
        for (int j = 0; j < 8; j++) atomicAdd(dst + j, acc[i][j]);
    }
}

// ---------------------------------------------------------------------------
// 5) stage 2: out[b,c,o] = bias[o] + sum_d tokens[b,c,d] * fcwT[d,o]
// ---------------------------------------------------------------------------
__global__ void k_stage2(const float* __restrict__ fc_b, float* __restrict__ out) {
    int b   = blockIdx.x;
    int ch0 = blockIdx.y * 8;
    int o   = threadIdx.x;     // 0..191
    __shared__ float4 tok[8][64];

    const float4* src = g_tokens4 + (b * NRINGS + ch0) * (TOKD / 4);
    for (int i = o; i < 8 * 64; i += OUTD)
        tok[i >> 6][i & 63] = src[i];
    __syncthreads();

    float bias = fc_b[o];
    float acc[8];
#pragma unroll
    for (int c = 0; c < 8; c++) acc[c] = bias;

    for (int d4 = 0; d4 < 64; d4++) {
        float w0 = g_fcwT[(d4 * 4 + 0) * OUTD + o];
        float w1 = g_fcwT[(d4 * 4 + 1) * OUTD + o];
        float w2 = g_fcwT[(d4 * 4 + 2) * OUTD + o];
        float w3 = g_fcwT[(d4 * 4 + 3) * OUTD + o];
#pragma unroll
        for (int c = 0; c < 8; c++) {
            float4 tv = tok[c][d4];
            acc[c] += tv.x * w0 + tv.y * w1 + tv.z * w2 + tv.w * w3;
        }
    }
#pragma unroll
    for (int c = 0; c < 8; c++)
        out[b * (NRINGS * OUTD) + (ch0 + c) * OUTD + o] = acc[c];
}

// ---------------------------------------------------------------------------
extern "C" void kernel_launch(void* const* d_in, const int* in_sizes, int n_in,
                              void* d_out, int out_size) {
    const float *x = nullptr, *W = nullptr, *fc_w = nullptr, *fc_b = nullptr,
                *masks = nullptr;
    for (int i = 0; i < n_in; i++) {
        switch (in_sizes[i]) {
            case B * P:            x     = (const float*)d_in[i]; break;
            case TOKD * P:         W     = (const float*)d_in[i]; break;
            case OUTD * TOKD:      fc_w  = (const float*)d_in[i]; break;
            case OUTD:             fc_b  = (const float*)d_in[i]; break;
            case NRINGS * P:       masks = (const float*)d_in[i]; break;
            default: break;
        }
    }
    if (!x || !W || !fc_w || !fc_b || !masks) {
        x     = (const float*)d_in[0];
        W     = (const float*)d_in[1];
        fc_w  = (const float*)d_in[2];
        fc_b  = (const float*)d_in[3];
        masks = (const float*)d_in[4];
    }
    float* out = (float*)d_out;

    k_zero_tokens   <<<256, 256>>>();
    k_transpose_fcw <<<(OUTD * TOKD / 4 + 255) / 256, 256>>>(fc_w);
    k_rid_count     <<<NTILES, 256>>>(masks);
    k_scan_chunks   <<<1, 512>>>();
    k_scatter       <<<NTILES, 256>>>();
    k_gemm_tokens   <<<dim3(MAXCHUNK, 2), 256>>>(x, W);
    k_stage2        <<<dim3(B, 2), OUTD>>>(fc_b, out);
}

// round 5
// speedup vs baseline: 1.6183x; 1.1855x over previous
#include <cuda_runtime.h>
#include <cuda_bf16.h>
#include <stdint.h>

// ---------------------------------------------------------------------------
// AnnularPatchEmbed — disjoint ring masks -> segmented GEMM over ring-sorted
// pixel list. R5: f32x2 packed-FMA inner loop (8x8/thread), fused prep kernel.
// ---------------------------------------------------------------------------

#define IMG      224
#define P        (IMG * IMG)       // 50176
#define B        64
#define NRINGS   16
#define TOKD     256
#define OUTD     192
#define NTILES   (P / 256)         // 196
#define KC       192               // K-chunk per GEMM block
#define KB       32                // K step inside GEMM block
#define MAXCHUNK 288
#define APAD     72                // As row stride (floats): 288B, 16B-aligned
#define BPAD     136               // Bs row stride (floats): 544B, 16B-aligned

typedef unsigned long long ull;

#define FMA_F32X2(d, a, b, c) \
    asm("fma.rn.f32x2 %0, %1, %2, %3;" : "=l"(d) : "l"(a), "l"(b), "l"(c))
#define PACK_F32X2(out, lo, hi) \
    asm("mov.b64 %0, {%1, %2};" : "=l"(out) : "f"(lo), "f"(hi))
#define UNPACK_F32X2(lo, hi, in) \
    asm("mov.b64 {%0, %1}, %2;" : "=f"(lo), "=f"(hi) : "l"(in))

// ---------------- device scratch (no allocations allowed) -----------------
__device__ unsigned char g_rid[P];
__device__ int   g_tileCnt[NTILES * NRINGS];
__device__ int   g_tileOff[NTILES * NRINGS];
__device__ int   g_ringBase[NRINGS + 1];
__device__ int   g_idx[P];
__device__ int   g_chunkRing[MAXCHUNK];
__device__ int   g_chunkK0[MAXCHUNK];
__device__ int   g_chunkLen[MAXCHUNK];
__device__ int   g_nChunks;
__device__ float4 g_tokens4[(B * NRINGS * TOKD) / 4];   // 1 MB
__device__ float  g_fcwT[TOKD * OUTD];

// ---------------------------------------------------------------------------
// 0) fused prep: [0,256) zero tokens | [256,304) transpose fc_w | [304,500) rid
// ---------------------------------------------------------------------------
__global__ void k_prep(const float* __restrict__ fc_w,
                       const float* __restrict__ masks) {
    int blk = blockIdx.x, t = threadIdx.x;

    if (blk < 256) {                              // zero 65536 float4
        g_tokens4[blk * 256 + t] = make_float4(0.f, 0.f, 0.f, 0.f);
        return;
    }
    if (blk < 304) {                              // transpose fc_w (12288 f4)
        int idx = (blk - 256) * 256 + t;
        if (idx < OUTD * TOKD / 4) {
            int o = idx / (TOKD / 4), d4 = idx % (TOKD / 4);
            float4 v = ((const float4*)fc_w)[idx];
            g_fcwT[(d4 * 4 + 0) * OUTD + o] = v.x;
            g_fcwT[(d4 * 4 + 1) * OUTD + o] = v.y;
            g_fcwT[(d4 * 4 + 2) * OUTD + o] = v.z;
            g_fcwT[(d4 * 4 + 3) * OUTD + o] = v.w;
        }
        return;
    }
    // ring id per pixel + per-tile ring histogram
    __shared__ int hist[NRINGS];
    int tile = blk - 304;
    if (t < NRINGS) hist[t] = 0;
    __syncthreads();
    int p = tile * 256 + t;
    int r = 255;
#pragma unroll
    for (int c = 0; c < NRINGS; c++)
        if (masks[c * P + p] > 0.5f) r = c;
    g_rid[p] = (unsigned char)r;
    if (r < NRINGS) atomicAdd(&hist[r], 1);
    __syncthreads();
    if (t < NRINGS) g_tileCnt[tile * NRINGS + t] = hist[t];
}

// ---------------------------------------------------------------------------
// 1) parallel scans + chunk build (16 warps, warp w = ring w)
// ---------------------------------------------------------------------------
__global__ void k_scan_chunks() {
    __shared__ int ringTot[NRINGS];
    __shared__ int ringBaseS[NRINGS];
    __shared__ int chunkBaseS[NRINGS];
    int t = threadIdx.x, w = t >> 5, lane = t & 31;

    if (w < NRINGS) {
        int run = 0;
        for (int base = 0; base < NTILES; base += 32) {
            int i = base + lane;
            int v = (i < NTILES) ? g_tileCnt[i * NRINGS + w] : 0;
            int s = v;
#pragma unroll
            for (int d = 1; d < 32; d <<= 1) {
                int n = __shfl_up_sync(0xffffffffu, s, d);
                if (lane >= d) s += n;
            }
            if (i < NTILES) g_tileOff[i * NRINGS + w] = run + s - v;
            run += __shfl_sync(0xffffffffu, s, 31);
        }
        if (lane == 0) ringTot[w] = run;
    }
    __syncthreads();

    if (w == 0) {
        int v = (lane < NRINGS) ? ringTot[lane] : 0;
        int s = v;
#pragma unroll
        for (int d = 1; d < 32; d <<= 1) {
            int n = __shfl_up_sync(0xffffffffu, s, d);
            if (lane >= d) s += n;
        }
        if (lane < NRINGS) { ringBaseS[lane] = s - v; g_ringBase[lane] = s - v; }
        if (lane == NRINGS - 1) g_ringBase[NRINGS] = s;

        int nc = (v + KC - 1) / KC;
        int cs = nc;
#pragma unroll
        for (int d = 1; d < 32; d <<= 1) {
            int n = __shfl_up_sync(0xffffffffu, cs, d);
            if (lane >= d) cs += n;
        }
        if (lane < NRINGS) chunkBaseS[lane] = cs - nc;
        if (lane == NRINGS - 1) g_nChunks = cs;
    }
    __syncthreads();

    if (w < NRINGS) {
        int tot = ringTot[w];
        int nc  = (tot + KC - 1) / KC;
        if (lane < nc) {
            int g = chunkBaseS[w] + lane;
            int k0 = lane * KC;
            g_chunkRing[g] = w;
            g_chunkK0[g]   = ringBaseS[w] + k0;
            g_chunkLen[g]  = min(KC, tot - k0);
        }
    }
}

// ---------------------------------------------------------------------------
// 2) single-pass stable ring-sorted compaction
// ---------------------------------------------------------------------------
__global__ void k_scatter() {
    __shared__ int wcnt[8][NRINGS];
    __shared__ int wpre[8][NRINGS];
    int t = threadIdx.x, tile = blockIdx.x;
    int lane = t & 31, w = t >> 5;

    if (t < 8 * NRINGS) ((int*)wcnt)[t] = 0;
    __syncthreads();

    int p = tile * 256 + t;
    int r = g_rid[p];
    unsigned peers = __match_any_sync(0xffffffffu, r);
    int lr = __popc(peers & ((1u << lane) - 1u));
    bool valid = (r < NRINGS);
    if (valid && lane == (__ffs(peers) - 1)) wcnt[w][r] = __popc(peers);
    __syncthreads();

    if (t < NRINGS) {
        int s = 0;
#pragma unroll
        for (int i = 0; i < 8; i++) { int v = wcnt[i][t]; wpre[i][t] = s; s += v; }
    }
    __syncthreads();

    if (valid) {
        int pos = g_ringBase[r] + g_tileOff[tile * NRINGS + r] + wpre[w][r] + lr;
        g_idx[pos] = p;
    }
}

// ---------------------------------------------------------------------------
// 3) segmented GEMM, f32x2 packed FMA. Block=(chunk, d-half), 128 threads,
//    8x8 outputs/thread over M=64 x N=128.
// ---------------------------------------------------------------------------
__global__ void __launch_bounds__(128, 4)
k_gemm_tokens(const float* __restrict__ x, const float* __restrict__ W) {
    int chunk = blockIdx.x;
    if (chunk >= g_nChunks) return;
    int ring  = g_chunkRing[chunk];
    int kbeg  = g_chunkK0[chunk];
    int klen  = g_chunkLen[chunk];
    int dBase = blockIdx.y * 128;

    __shared__ float As[KB][APAD];   // As[k][m] = x[m, p_k]
    __shared__ float Bs[KB][BPAD];   // Bs[k][n] = W[dBase+n, p_k]

    int t    = threadIdx.x;          // 0..127
    int mi   = t >> 4;               // 0..7  -> rows mi*8..+7
    int ni   = t & 15;               // 0..15 -> cols ni*8..+7
    int lane = t & 31;               // k slot loaded by this thread
    int w    = t >> 5;               // 0..3

    ull acc[8][4];
#pragma unroll
    for (int i = 0; i < 8; i++)
#pragma unroll
        for (int j = 0; j < 4; j++) acc[i][j] = 0ull;

    for (int kk = 0; kk < klen; kk += KB) {
        int k  = kk + lane;
        int pp = (k < klen) ? g_idx[kbeg + k] : -1;

        if (pp >= 0) {
#pragma unroll
            for (int i = 0; i < 16; i++)                 // A: rows w*16..+15
                As[lane][w * 16 + i] = x[(w * 16 + i) * P + pp];
#pragma unroll
            for (int i = 0; i < 32; i++)                 // B: cols w*32..+31
                Bs[lane][w * 32 + i] = W[(dBase + w * 32 + i) * P + pp];
        } else {
#pragma unroll
            for (int i = 0; i < 16; i++) As[lane][w * 16 + i] = 0.f;
#pragma unroll
            for (int i = 0; i < 32; i++) Bs[lane][w * 32 + i] = 0.f;
        }
        __syncthreads();

#pragma unroll
        for (int k2 = 0; k2 < KB; k2++) {
            float4 aL = *(const float4*)&As[k2][mi * 8];
            float4 aH = *(const float4*)&As[k2][mi * 8 + 4];
            ulonglong2 bL = *(const ulonglong2*)&Bs[k2][ni * 8];
            ulonglong2 bH = *(const ulonglong2*)&Bs[k2][ni * 8 + 4];
            ull b[4] = { bL.x, bL.y, bH.x, bH.y };

            ull a2[8];
            PACK_F32X2(a2[0], aL.x, aL.x);
            PACK_F32X2(a2[1], aL.y, aL.y);
            PACK_F32X2(a2[2], aL.z, aL.z);
            PACK_F32X2(a2[3], aL.w, aL.w);
            PACK_F32X2(a2[4], aH.x, aH.x);
            PACK_F32X2(a2[5], aH.y, aH.y);
            PACK_F32X2(a2[6], aH.z, aH.z);
            PACK_F32X2(a2[7], aH.w, aH.w);

#pragma unroll
            for (int i = 0; i < 8; i++) {
#pragma unroll
                for (int j = 0; j < 4; j++)
                    FMA_F32X2(acc[i][j], a2[i], b[j], acc[i][j]);
            }
        }
        __syncthreads();
    }

    float* tokens = (float*)g_tokens4;
#pragma unroll
    for (int i = 0; i < 8; i++) {
        int bb = mi * 8 + i;
        float* dst = tokens + bb * (NRINGS * TOKD) + ring * TOKD + dBase + ni * 8;
#pragma unroll
        for (int j = 0; j < 4; j++) {
            float lo, hi;
            UNPACK_F32X2(lo, hi, acc[i][j]);
            atomicAdd(dst + 2 * j,     lo);
            atomicAdd(dst + 2 * j + 1, hi);
        }
    }
}

// ---------------------------------------------------------------------------
// 4) stage 2: out[b,c,o] = bias[o] + sum_d tokens[b,c,d] * fcwT[d,o]
// ---------------------------------------------------------------------------
__global__ void k_stage2(const float* __restrict__ fc_b, float* __restrict__ out) {
    int b   = blockIdx.x;
    int ch0 = blockIdx.y * 8;
    int o   = threadIdx.x;     // 0..191
    __shared__ float4 tok[8][64];

    const float4* src = g_tokens4 + (b * NRINGS + ch0) * (TOKD / 4);
    for (int i = o; i < 8 * 64; i += OUTD)
        tok[i >> 6][i & 63] = src[i];
    __syncthreads();

    float bias = fc_b[o];
    float acc[8];
#pragma unroll
    for (int c = 0; c < 8; c++) acc[c] = bias;

    for (int d4 = 0; d4 < 64; d4++) {
        float w0 = g_fcwT[(d4 * 4 + 0) * OUTD + o];
        float w1 = g_fcwT[(d4 * 4 + 1) * OUTD + o];
        float w2 = g_fcwT[(d4 * 4 + 2) * OUTD + o];
        float w3 = g_fcwT[(d4 * 4 + 3) * OUTD + o];
#pragma unroll
        for (int c = 0; c < 8; c++) {
            float4 tv = tok[c][d4];
            acc[c] += tv.x * w0 + tv.y * w1 + tv.z * w2 + tv.w * w3;
        }
    }
#pragma unroll
    for (int c = 0; c < 8; c++)
        out[b * (NRINGS * OUTD) + (ch0 + c) * OUTD + o] = acc[c];
}

// ---------------------------------------------------------------------------
extern "C" void kernel_launch(void* const* d_in, const int* in_sizes, int n_in,
                              void* d_out, int out_size) {
    const float *x = nullptr, *W = nullptr, *fc_w = nullptr, *fc_b = nullptr,
                *masks = nullptr;
    for (int i = 0; i < n_in; i++) {
        switch (in_sizes[i]) {
            case B * P:            x     = (const float*)d_in[i]; break;
            case TOKD * P:         W     = (const float*)d_in[i]; break;
            case OUTD * TOKD:      fc_w  = (const float*)d_in[i]; break;
            case OUTD:             fc_b  = (const float*)d_in[i]; break;
            case NRINGS * P:       masks = (const float*)d_in[i]; break;
            default: break;
        }
    }
    if (!x || !W || !fc_w || !fc_b || !masks) {
        x     = (const float*)d_in[0];
        W     = (const float*)d_in[1];
        fc_w  = (const float*)d_in[2];
        fc_b  = (const float*)d_in[3];
        masks = (const float*)d_in[4];
    }
    float* out = (float*)d_out;

    k_prep        <<<256 + 48 + NTILES, 256>>>(fc_w, masks);   // launch 0
    k_scan_chunks <<<1, 512>>>();                              // launch 1
    k_scatter     <<<NTILES, 256>>>();                         // launch 2
    k_gemm_tokens <<<dim3(MAXCHUNK, 2), 128>>>(x, W);          // launch 3
    k_stage2      <<<dim3(B, 2), OUTD>>>(fc_b, out);           // launch 4
}